// round 7
// baseline (speedup 1.0000x reference)
#include <cuda_runtime.h>
#include <cuda_bf16.h>
#include <mma.h>
#include <cstdint>

using namespace nvcuda;

#define NBATCH 8192
#define SETS   4
#define GRID   (NBATCH/SETS)
#define TPB    512
#define NLAT   16

// ---------------- shared memory layout (bytes) ----------------
#define O_W2HI 0        // bf16 [128][136]  = 34816
#define O_W2LO 34816    // bf16 [128][136]  = 34816
#define O_W3HI 69632    // bf16 [128][40]   = 10240
#define O_W3LO 79872    // bf16 [128][40]   = 10240
#define O_A    90112    // A1hi bf16 [128][136] = 34816 ; A1lo at +34816 (total 69632)
#define O_AHI  90112
#define O_ALO  124928
#define O_HT   90112    // fp32 [128][132] = 67584 (aliases A region after layer2)
#define O_WP   159744   // f32 [32][128] = 16384
#define O_KEY  176128   // u32 [32][132] = 16896
#define O_ZC   193024   // f32 [32][132] = 16896
#define O_X    209920   // 2048
#define O_W1   211968   // 2048
#define O_B1   214016   // 512
#define O_B2   214528   // 512
#define O_B3   215040   // 128
#define O_PL   215168   // 128
#define SMEM_BYTES 215296

__global__ __launch_bounds__(TPB, 1)
void enc_kernel(const float* __restrict__ x,  const float* __restrict__ W1,
                const float* __restrict__ b1, const float* __restrict__ W2,
                const float* __restrict__ b2, const float* __restrict__ W3,
                const float* __restrict__ b3, const float* __restrict__ pwm,
                const float* __restrict__ eps, float* __restrict__ out)
{
    extern __shared__ __align__(1024) char smem[];
    const int tid = threadIdx.x;
    const int wid = tid >> 5, lane = tid & 31;

    __nv_bfloat16* sW2hi = (__nv_bfloat16*)(smem + O_W2HI);
    __nv_bfloat16* sW2lo = (__nv_bfloat16*)(smem + O_W2LO);
    __nv_bfloat16* sW3hi = (__nv_bfloat16*)(smem + O_W3HI);
    __nv_bfloat16* sW3lo = (__nv_bfloat16*)(smem + O_W3LO);
    __nv_bfloat16* sAhi  = (__nv_bfloat16*)(smem + O_AHI);
    __nv_bfloat16* sAlo  = (__nv_bfloat16*)(smem + O_ALO);
    float*         sHt   = (float*)(smem + O_HT);
    float*         sWp   = (float*)(smem + O_WP);
    unsigned*      sKey  = (unsigned*)(smem + O_KEY);
    float*         sZc   = (float*)(smem + O_ZC);

    // ---------- stage invariant weights (hi/lo bf16 split) ----------
    {
        #pragma unroll 4
        for (int r = 0; r < 32; r++) {
            int i = tid + r * TPB;             // i = j*128 + k
            float v = W2[i];
            __nv_bfloat16 hi = __float2bfloat16_rn(v);
            __nv_bfloat16 lo = __float2bfloat16_rn(v - __bfloat162float(hi));
            int j = i >> 7, k = i & 127;
            sW2hi[j*136 + k] = hi;
            sW2lo[j*136 + k] = lo;
        }
        #pragma unroll
        for (int r = 0; r < 8; r++) {
            int i = tid + r * TPB;             // i = k*32 + c
            float v = W3[i];
            __nv_bfloat16 hi = __float2bfloat16_rn(v);
            __nv_bfloat16 lo = __float2bfloat16_rn(v - __bfloat162float(hi));
            int k = i >> 5, c = i & 31;
            sW3hi[k*40 + c] = hi;
            sW3lo[k*40 + c] = lo;
        }
        if (tid < 128) ((float4*)(smem + O_W1))[tid] = ((const float4*)W1)[tid];
        if (tid >= 128 && tid < 160) ((float4*)(smem + O_B1))[tid-128] = ((const float4*)b1)[tid-128];
        if (tid >= 160 && tid < 192) ((float4*)(smem + O_B2))[tid-160] = ((const float4*)b2)[tid-160];
        if (tid >= 192 && tid < 200) ((float4*)(smem + O_B3))[tid-192] = ((const float4*)b3)[tid-192];
        for (int i = tid; i < 4096; i += TPB) {
            int c = i >> 7, pp = i & 127;
            float pos = (float)pp / 127.0f * 20.0f;
            int idx = (int)pos; if (idx > 20) idx = 20;
            float frac = pos - (float)idx;
            int idx2 = idx + 1; if (idx2 > 20) idx2 = 20;
            sWp[i] = (1.0f - frac) * pwm[c*21 + idx] + frac * pwm[c*21 + idx2];
        }
    }

    for (int s = 0; s < SETS; s++) {
        const int bset = blockIdx.x * SETS + s;
        __syncthreads();   // weights staged / previous set fully done
        if (tid < 128) ((float4*)(smem + O_X))[tid] = ((const float4*)(x + (size_t)bset * 512))[tid];
        __syncthreads();

        // ---------- layer 1 -> A1 hi/lo bf16 [p][j], stride 136 ----------
        {
            const float* sX  = (const float*)(smem + O_X);
            const float* sW1 = (const float*)(smem + O_W1);
            const float* sb1 = (const float*)(smem + O_B1);
            const int p = tid >> 2, j0 = (tid & 3) * 32;
            float x0 = sX[p*4+0], x1 = sX[p*4+1], x2 = sX[p*4+2], x3 = sX[p*4+3];
            #pragma unroll 8
            for (int j = j0; j < j0 + 32; j++) {
                float a = sb1[j];
                a = fmaf(x0, sW1[j],       a);
                a = fmaf(x1, sW1[128 + j], a);
                a = fmaf(x2, sW1[256 + j], a);
                a = fmaf(x3, sW1[384 + j], a);
                a = fmaxf(a, 0.0f);
                __nv_bfloat16 hi = __float2bfloat16_rn(a);
                __nv_bfloat16 lo = __float2bfloat16_rn(a - __bfloat162float(hi));
                sAhi[p*136 + j] = hi;
                sAlo[p*136 + j] = lo;
            }
        }
        __syncthreads();

        // ---------- layer 2: C[128x128] = H1 x W2 (16 warps, 32x32 tiles) ----------
        {
            const int wm = wid >> 2, wn = wid & 3;
            const int m0 = wm * 32, n0 = wn * 32;
            wmma::fragment<wmma::accumulator, 16,16,16, float> c[2][2];
            #pragma unroll
            for (int i = 0; i < 2; i++)
                #pragma unroll
                for (int j = 0; j < 2; j++) wmma::fill_fragment(c[i][j], 0.0f);

            #pragma unroll
            for (int kk = 0; kk < 8; kk++) {
                const int k0 = kk * 16;
                wmma::fragment<wmma::matrix_a, 16,16,16, __nv_bfloat16, wmma::row_major> ahi[2], alo[2];
                wmma::fragment<wmma::matrix_b, 16,16,16, __nv_bfloat16, wmma::row_major> bhi[2], blo[2];
                #pragma unroll
                for (int i = 0; i < 2; i++) {
                    wmma::load_matrix_sync(ahi[i], sAhi + (m0 + 16*i)*136 + k0, 136);
                    wmma::load_matrix_sync(alo[i], sAlo + (m0 + 16*i)*136 + k0, 136);
                }
                #pragma unroll
                for (int j = 0; j < 2; j++) {
                    wmma::load_matrix_sync(bhi[j], sW2hi + k0*136 + n0 + 16*j, 136);
                    wmma::load_matrix_sync(blo[j], sW2lo + k0*136 + n0 + 16*j, 136);
                }
                #pragma unroll
                for (int i = 0; i < 2; i++)
                    #pragma unroll
                    for (int j = 0; j < 2; j++) {
                        wmma::mma_sync(c[i][j], ahi[i], bhi[j], c[i][j]);
                        wmma::mma_sync(c[i][j], ahi[i], blo[j], c[i][j]);
                        wmma::mma_sync(c[i][j], alo[i], bhi[j], c[i][j]);
                    }
            }
            __syncthreads();   // all warps done reading A1 -> safe to overwrite via sHt
            #pragma unroll
            for (int i = 0; i < 2; i++)
                #pragma unroll
                for (int j = 0; j < 2; j++)
                    wmma::store_matrix_sync(sHt + (m0 + 16*i)*132 + n0 + 16*j, c[i][j], 132, wmma::mem_row_major);
        }
        __syncthreads();

        // ---------- epilogue1: h2 = relu(Ht + b2) -> A2 hi/lo (aliased region) ----------
        {
            const float* sb2 = (const float*)(smem + O_B2);
            const int p = tid >> 2, k0 = (tid & 3) * 32;
            float v[32];
            #pragma unroll 8
            for (int k = 0; k < 32; k++)
                v[k] = fmaxf(sHt[p*132 + k0 + k] + sb2[k0 + k], 0.0f);
            __syncthreads();   // all reads of Ht done before overwriting with A2
            #pragma unroll 8
            for (int k = 0; k < 32; k++) {
                __nv_bfloat16 hi = __float2bfloat16_rn(v[k]);
                __nv_bfloat16 lo = __float2bfloat16_rn(v[k] - __bfloat162float(hi));
                sAhi[p*136 + k0 + k] = hi;
                sAlo[p*136 + k0 + k] = lo;
            }
        }
        __syncthreads();

        // ---------- layer 3: Z[128x32] = H2 x W3 (8 warps, 32x16 tiles) ----------
        if (wid < 8) {
            const int wm = wid >> 1, wn = wid & 1;
            const int m0 = wm * 32, n0 = wn * 16;
            wmma::fragment<wmma::accumulator, 16,16,16, float> c3[2];
            wmma::fill_fragment(c3[0], 0.0f);
            wmma::fill_fragment(c3[1], 0.0f);
            #pragma unroll
            for (int kk = 0; kk < 8; kk++) {
                const int k0 = kk * 16;
                wmma::fragment<wmma::matrix_a, 16,16,16, __nv_bfloat16, wmma::row_major> ahi[2], alo[2];
                wmma::fragment<wmma::matrix_b, 16,16,16, __nv_bfloat16, wmma::row_major> bhi, blo;
                #pragma unroll
                for (int i = 0; i < 2; i++) {
                    wmma::load_matrix_sync(ahi[i], sAhi + (m0 + 16*i)*136 + k0, 136);
                    wmma::load_matrix_sync(alo[i], sAlo + (m0 + 16*i)*136 + k0, 136);
                }
                wmma::load_matrix_sync(bhi, sW3hi + k0*40 + n0, 40);
                wmma::load_matrix_sync(blo, sW3lo + k0*40 + n0, 40);
                #pragma unroll
                for (int i = 0; i < 2; i++) {
                    wmma::mma_sync(c3[i], ahi[i], bhi, c3[i]);
                    wmma::mma_sync(c3[i], ahi[i], blo, c3[i]);
                    wmma::mma_sync(c3[i], alo[i], bhi, c3[i]);
                }
            }
            // store transposed into ZC: element (m,n) -> sZc[(n0+n)*132 + (m0+m)]
            wmma::store_matrix_sync(sZc + n0*132 + m0,      c3[0], 132, wmma::mem_col_major);
            wmma::store_matrix_sync(sZc + n0*132 + m0 + 16, c3[1], 132, wmma::mem_col_major);
        }
        __syncthreads();

        // ---------- bias + sort keys ----------
        {
            const float* sb3 = (const float*)(smem + O_B3);
            #pragma unroll
            for (int r = 0; r < 8; r++) {
                int i = tid + r * TPB;           // 4096 = 32ch * 128p
                int c = i >> 7, p = i & 127;
                float zv = sZc[c*132 + p] + sb3[c];
                sZc[c*132 + p] = zv;
                unsigned u = __float_as_uint(zv);
                unsigned s2 = (u & 0x80000000u) ? ~u : (u | 0x80000000u);
                sKey[c*132 + p] = (s2 & 0xFFFFFF80u) | (unsigned)(127 - p);
            }
        }
        __syncthreads();

        // ---------- ranking + weighted pool (2 channels per warp) ----------
        {
            float* sPl = (float*)(smem + O_PL);
            #pragma unroll
            for (int cc = 0; cc < 2; cc++) {
                const int c = wid * 2 + cc;
                const unsigned* kp = sKey + c * 132;
                const float* zp = sZc + c * 132;
                unsigned k0_ = kp[lane], k1 = kp[lane+32], k2 = kp[lane+64], k3 = kp[lane+96];
                int r0 = 0, r1 = 0, r2 = 0, r3 = 0;
                const uint4* kq4 = (const uint4*)kp;
                #pragma unroll 8
                for (int qq = 0; qq < 32; qq++) {
                    uint4 kq = kq4[qq];
                    r0 += (kq.x > k0_) + (kq.y > k0_) + (kq.z > k0_) + (kq.w > k0_);
                    r1 += (kq.x > k1)  + (kq.y > k1)  + (kq.z > k1)  + (kq.w > k1);
                    r2 += (kq.x > k2)  + (kq.y > k2)  + (kq.z > k2)  + (kq.w > k2);
                    r3 += (kq.x > k3)  + (kq.y > k3)  + (kq.z > k3)  + (kq.w > k3);
                }
                const float* wc = sWp + c * 128;
                float sum = zp[lane]    * wc[r0]
                          + zp[lane+32] * wc[r1]
                          + zp[lane+64] * wc[r2]
                          + zp[lane+96] * wc[r3];
                #pragma unroll
                for (int ofs = 16; ofs > 0; ofs >>= 1)
                    sum += __shfl_xor_sync(0xffffffffu, sum, ofs);
                if (lane == 0) sPl[c] = sum;
            }
        }
        __syncthreads();

        // ---------- reparameterize + write ----------
        if (tid < NLAT) {
            const float* sPl = (const float*)(smem + O_PL);
            float mu = sPl[2*tid];
            float lv = sPl[2*tid + 1];
            float e  = eps[(size_t)bset*NLAT + tid];
            float smp = fmaf(e, expf(0.5f * lv), mu);
            out[(size_t)bset*NLAT + tid] = mu;
            out[(size_t)(NBATCH*NLAT)   + (size_t)bset*NLAT + tid] = lv;
            out[(size_t)(2*NBATCH*NLAT) + (size_t)bset*NLAT + tid] = smp;
        }
    }
}

extern "C" void kernel_launch(void* const* d_in, const int* in_sizes, int n_in,
                              void* d_out, int out_size) {
    const float* x   = (const float*)d_in[0];
    const float* W1  = (const float*)d_in[1];
    const float* b1  = (const float*)d_in[2];
    const float* W2  = (const float*)d_in[3];
    const float* b2  = (const float*)d_in[4];
    const float* W3  = (const float*)d_in[5];
    const float* b3  = (const float*)d_in[6];
    const float* pwm = (const float*)d_in[7];
    const float* eps = (const float*)d_in[8];
    float* out = (float*)d_out;

    cudaFuncSetAttribute(enc_kernel, cudaFuncAttributeMaxDynamicSharedMemorySize, SMEM_BYTES);
    enc_kernel<<<GRID, TPB, SMEM_BYTES>>>(x, W1, b1, W2, b2, W3, b3, pwm, eps, out);
}

// round 8
// speedup vs baseline: 1.9352x; 1.9352x over previous
#include <cuda_runtime.h>
#include <cuda_bf16.h>
#include <mma.h>
#include <cstdint>

using namespace nvcuda;

#define NBATCH 8192
#define SETS   4
#define GRID   (NBATCH/SETS)
#define TPB    512
#define NLAT   16

// ---------------- shared memory layout (bytes) ----------------
#define O_W2HI 0        // bf16 [128][136]  = 34816
#define O_W2LO 34816    // bf16 [128][136]  = 34816
#define O_W3HI 69632    // bf16 [128][40]   = 10240
#define O_W3LO 79872    // bf16 [128][40]   = 10240
#define O_AHI  90112    // A hi bf16 [128][136] = 34816
#define O_ALO  124928   // A lo bf16 [128][136] = 34816
#define O_HT   90112    // fp32 [128][132] = 67584 (aliases A region between layer2/epi1)
#define O_WP   159744   // f32 [32][128] = 16384
#define O_ZC   176128   // f32 [32][132] = 16896
#define O_X    193024   // 2048
#define O_W1   195072   // 2048
#define O_B1   197120   // 512
#define O_B2   197632   // 512
#define O_B3   198144   // 128
#define O_PL   198272   // 128
#define SMEM_BYTES 198400

__global__ __launch_bounds__(TPB, 1)
void enc_kernel(const float* __restrict__ x,  const float* __restrict__ W1,
                const float* __restrict__ b1, const float* __restrict__ W2,
                const float* __restrict__ b2, const float* __restrict__ W3,
                const float* __restrict__ b3, const float* __restrict__ pwm,
                const float* __restrict__ eps, float* __restrict__ out)
{
    extern __shared__ __align__(1024) char smem[];
    const int tid = threadIdx.x;
    const int wid = tid >> 5, lane = tid & 31;

    __nv_bfloat16* sW2hi = (__nv_bfloat16*)(smem + O_W2HI);
    __nv_bfloat16* sW2lo = (__nv_bfloat16*)(smem + O_W2LO);
    __nv_bfloat16* sW3hi = (__nv_bfloat16*)(smem + O_W3HI);
    __nv_bfloat16* sW3lo = (__nv_bfloat16*)(smem + O_W3LO);
    __nv_bfloat16* sAhi  = (__nv_bfloat16*)(smem + O_AHI);
    __nv_bfloat16* sAlo  = (__nv_bfloat16*)(smem + O_ALO);
    float*         sHt   = (float*)(smem + O_HT);
    float*         sWp   = (float*)(smem + O_WP);
    float*         sZc   = (float*)(smem + O_ZC);

    // ---------- stage invariant weights (hi/lo bf16 split) ----------
    {
        #pragma unroll 4
        for (int r = 0; r < 32; r++) {
            int i = tid + r * TPB;             // i = j*128 + k
            float v = W2[i];
            __nv_bfloat16 hi = __float2bfloat16_rn(v);
            __nv_bfloat16 lo = __float2bfloat16_rn(v - __bfloat162float(hi));
            int j = i >> 7, k = i & 127;
            sW2hi[j*136 + k] = hi;
            sW2lo[j*136 + k] = lo;
        }
        #pragma unroll
        for (int r = 0; r < 8; r++) {
            int i = tid + r * TPB;             // i = k*32 + c
            float v = W3[i];
            __nv_bfloat16 hi = __float2bfloat16_rn(v);
            __nv_bfloat16 lo = __float2bfloat16_rn(v - __bfloat162float(hi));
            int k = i >> 5, c = i & 31;
            sW3hi[k*40 + c] = hi;
            sW3lo[k*40 + c] = lo;
        }
        if (tid < 128) ((float4*)(smem + O_W1))[tid] = ((const float4*)W1)[tid];
        if (tid >= 128 && tid < 160) ((float4*)(smem + O_B1))[tid-128] = ((const float4*)b1)[tid-128];
        if (tid >= 160 && tid < 192) ((float4*)(smem + O_B2))[tid-160] = ((const float4*)b2)[tid-160];
        if (tid >= 192 && tid < 200) ((float4*)(smem + O_B3))[tid-192] = ((const float4*)b3)[tid-192];
        for (int i = tid; i < 4096; i += TPB) {
            int c = i >> 7, pp = i & 127;
            float pos = (float)pp / 127.0f * 20.0f;
            int idx = (int)pos; if (idx > 20) idx = 20;
            float frac = pos - (float)idx;
            int idx2 = idx + 1; if (idx2 > 20) idx2 = 20;
            sWp[i] = (1.0f - frac) * pwm[c*21 + idx] + frac * pwm[c*21 + idx2];
        }
    }

    for (int s = 0; s < SETS; s++) {
        const int bset = blockIdx.x * SETS + s;
        __syncthreads();
        if (tid < 128) ((float4*)(smem + O_X))[tid] = ((const float4*)(x + (size_t)bset * 512))[tid];
        __syncthreads();

        // ---------- layer 1 -> A1 hi/lo bf16 [p][j], stride 136 ----------
        {
            const float* sX  = (const float*)(smem + O_X);
            const float* sW1 = (const float*)(smem + O_W1);
            const float* sb1 = (const float*)(smem + O_B1);
            const int p = tid >> 2, j0 = (tid & 3) * 32;
            float x0 = sX[p*4+0], x1 = sX[p*4+1], x2 = sX[p*4+2], x3 = sX[p*4+3];
            #pragma unroll 8
            for (int j = j0; j < j0 + 32; j++) {
                float a = sb1[j];
                a = fmaf(x0, sW1[j],       a);
                a = fmaf(x1, sW1[128 + j], a);
                a = fmaf(x2, sW1[256 + j], a);
                a = fmaf(x3, sW1[384 + j], a);
                a = fmaxf(a, 0.0f);
                __nv_bfloat16 hi = __float2bfloat16_rn(a);
                __nv_bfloat16 lo = __float2bfloat16_rn(a - __bfloat162float(hi));
                sAhi[p*136 + j] = hi;
                sAlo[p*136 + j] = lo;
            }
        }
        __syncthreads();

        // ---------- layer 2: C[128x128] = H1 x W2 (16 warps, 32x32 tiles) ----------
        {
            const int wm = wid >> 2, wn = wid & 3;
            const int m0 = wm * 32, n0 = wn * 32;
            wmma::fragment<wmma::accumulator, 16,16,16, float> c[2][2];
            #pragma unroll
            for (int i = 0; i < 2; i++)
                #pragma unroll
                for (int j = 0; j < 2; j++) wmma::fill_fragment(c[i][j], 0.0f);

            #pragma unroll
            for (int kk = 0; kk < 8; kk++) {
                const int k0 = kk * 16;
                wmma::fragment<wmma::matrix_a, 16,16,16, __nv_bfloat16, wmma::row_major> ahi[2], alo[2];
                wmma::fragment<wmma::matrix_b, 16,16,16, __nv_bfloat16, wmma::row_major> bhi[2], blo[2];
                #pragma unroll
                for (int i = 0; i < 2; i++) {
                    wmma::load_matrix_sync(ahi[i], sAhi + (m0 + 16*i)*136 + k0, 136);
                    wmma::load_matrix_sync(alo[i], sAlo + (m0 + 16*i)*136 + k0, 136);
                }
                #pragma unroll
                for (int j = 0; j < 2; j++) {
                    wmma::load_matrix_sync(bhi[j], sW2hi + k0*136 + n0 + 16*j, 136);
                    wmma::load_matrix_sync(blo[j], sW2lo + k0*136 + n0 + 16*j, 136);
                }
                #pragma unroll
                for (int i = 0; i < 2; i++)
                    #pragma unroll
                    for (int j = 0; j < 2; j++) {
                        wmma::mma_sync(c[i][j], ahi[i], bhi[j], c[i][j]);
                        wmma::mma_sync(c[i][j], ahi[i], blo[j], c[i][j]);
                        wmma::mma_sync(c[i][j], alo[i], bhi[j], c[i][j]);
                    }
            }
            __syncthreads();   // all warps done reading A1 -> safe to overwrite via sHt
            #pragma unroll
            for (int i = 0; i < 2; i++)
                #pragma unroll
                for (int j = 0; j < 2; j++)
                    wmma::store_matrix_sync(sHt + (m0 + 16*i)*132 + n0 + 16*j, c[i][j], 132, wmma::mem_row_major);
        }
        __syncthreads();

        // ---------- epilogue1: h2 = relu(Ht + b2) -> A2 hi/lo (aliased region) ----------
        {
            const float* sb2 = (const float*)(smem + O_B2);
            const int p = tid >> 2, k0 = (tid & 3) * 32;
            float v[32];
            #pragma unroll 8
            for (int k = 0; k < 32; k++)
                v[k] = fmaxf(sHt[p*132 + k0 + k] + sb2[k0 + k], 0.0f);
            __syncthreads();   // all reads of Ht done before overwriting with A2
            #pragma unroll 8
            for (int k = 0; k < 32; k++) {
                __nv_bfloat16 hi = __float2bfloat16_rn(v[k]);
                __nv_bfloat16 lo = __float2bfloat16_rn(v[k] - __bfloat162float(hi));
                sAhi[p*136 + k0 + k] = hi;
                sAlo[p*136 + k0 + k] = lo;
            }
        }
        __syncthreads();

        // ---------- layer 3: Z[128x32] = H2 x W3 (8 warps, 32x16 tiles) ----------
        if (wid < 8) {
            const int wm = wid >> 1, wn = wid & 1;
            const int m0 = wm * 32, n0 = wn * 16;
            wmma::fragment<wmma::accumulator, 16,16,16, float> c3[2];
            wmma::fill_fragment(c3[0], 0.0f);
            wmma::fill_fragment(c3[1], 0.0f);
            #pragma unroll
            for (int kk = 0; kk < 8; kk++) {
                const int k0 = kk * 16;
                wmma::fragment<wmma::matrix_a, 16,16,16, __nv_bfloat16, wmma::row_major> ahi[2], alo[2];
                wmma::fragment<wmma::matrix_b, 16,16,16, __nv_bfloat16, wmma::row_major> bhi, blo;
                #pragma unroll
                for (int i = 0; i < 2; i++) {
                    wmma::load_matrix_sync(ahi[i], sAhi + (m0 + 16*i)*136 + k0, 136);
                    wmma::load_matrix_sync(alo[i], sAlo + (m0 + 16*i)*136 + k0, 136);
                }
                wmma::load_matrix_sync(bhi, sW3hi + k0*40 + n0, 40);
                wmma::load_matrix_sync(blo, sW3lo + k0*40 + n0, 40);
                #pragma unroll
                for (int i = 0; i < 2; i++) {
                    wmma::mma_sync(c3[i], ahi[i], bhi, c3[i]);
                    wmma::mma_sync(c3[i], ahi[i], blo, c3[i]);
                    wmma::mma_sync(c3[i], alo[i], bhi, c3[i]);
                }
            }
            // store transposed into ZC: element (m,n) -> sZc[(n0+n)*132 + (m0+m)]
            wmma::store_matrix_sync(sZc + n0*132 + m0,      c3[0], 132, wmma::mem_col_major);
            wmma::store_matrix_sync(sZc + n0*132 + m0 + 16, c3[1], 132, wmma::mem_col_major);
        }
        __syncthreads();

        // ---------- bitonic sorted-dot pool (2 channels per warp) ----------
        {
            const float* sb3 = (const float*)(smem + O_B3);
            float* sPl = (float*)(smem + O_PL);
            #pragma unroll
            for (int cc = 0; cc < 2; cc++) {
                const int c = wid * 2 + cc;
                const float bias = sb3[c];
                const float* zp = sZc + c * 132;
                // load 4 values: virtual index = r*32 + lane
                float v[4];
                #pragma unroll
                for (int r = 0; r < 4; r++) v[r] = zp[r*32 + lane] + bias;

                // bitonic sort ascending over 128 values
                #pragma unroll
                for (int k = 2; k <= 128; k <<= 1) {
                    #pragma unroll
                    for (int st = 64; st >= 1; st >>= 1) {
                        if (st >= k) continue;
                        if (st < 32) {
                            const bool lower = ((lane & st) == 0);
                            #pragma unroll
                            for (int r = 0; r < 4; r++) {
                                float o = __shfl_xor_sync(0xffffffffu, v[r], st);
                                bool up = (((r*32 + lane) & k) == 0);
                                bool tmin = (up == lower);
                                float mn = fminf(v[r], o), mx = fmaxf(v[r], o);
                                v[r] = tmin ? mn : mx;
                            }
                        } else if (st == 32) {
                            #pragma unroll
                            for (int ra = 0; ra < 4; ra += 2) {
                                bool up = (((ra*32) & k) == 0);
                                float mn = fminf(v[ra], v[ra+1]), mx = fmaxf(v[ra], v[ra+1]);
                                v[ra]   = up ? mn : mx;
                                v[ra+1] = up ? mx : mn;
                            }
                        } else {    // st == 64 (k == 128, ascending)
                            #pragma unroll
                            for (int ra = 0; ra < 2; ra++) {
                                float mn = fminf(v[ra], v[ra+2]), mx = fmaxf(v[ra], v[ra+2]);
                                v[ra]   = mn;
                                v[ra+2] = mx;
                            }
                        }
                    }
                }

                // ascending position idx = r*32+lane  ->  descending rank = 127-idx
                const float* wc = sWp + c * 128;
                float sum = v[0] * wc[127 - lane]
                          + v[1] * wc[95  - lane]
                          + v[2] * wc[63  - lane]
                          + v[3] * wc[31  - lane];
                #pragma unroll
                for (int ofs = 16; ofs > 0; ofs >>= 1)
                    sum += __shfl_xor_sync(0xffffffffu, sum, ofs);
                if (lane == 0) sPl[c] = sum;
            }
        }
        __syncthreads();

        // ---------- reparameterize + write ----------
        if (tid < NLAT) {
            const float* sPl = (const float*)(smem + O_PL);
            float mu = sPl[2*tid];
            float lv = sPl[2*tid + 1];
            float e  = eps[(size_t)bset*NLAT + tid];
            float smp = fmaf(e, expf(0.5f * lv), mu);
            out[(size_t)bset*NLAT + tid] = mu;
            out[(size_t)(NBATCH*NLAT)   + (size_t)bset*NLAT + tid] = lv;
            out[(size_t)(2*NBATCH*NLAT) + (size_t)bset*NLAT + tid] = smp;
        }
    }
}

extern "C" void kernel_launch(void* const* d_in, const int* in_sizes, int n_in,
                              void* d_out, int out_size) {
    const float* x   = (const float*)d_in[0];
    const float* W1  = (const float*)d_in[1];
    const float* b1  = (const float*)d_in[2];
    const float* W2  = (const float*)d_in[3];
    const float* b2  = (const float*)d_in[4];
    const float* W3  = (const float*)d_in[5];
    const float* b3  = (const float*)d_in[6];
    const float* pwm = (const float*)d_in[7];
    const float* eps = (const float*)d_in[8];
    float* out = (float*)d_out;

    cudaFuncSetAttribute(enc_kernel, cudaFuncAttributeMaxDynamicSharedMemorySize, SMEM_BYTES);
    enc_kernel<<<GRID, TPB, SMEM_BYTES>>>(x, W1, b1, W2, b2, W3, b3, pwm, eps, out);
}

// round 10
// speedup vs baseline: 2.0490x; 1.0588x over previous
#include <cuda_runtime.h>
#include <cuda_bf16.h>
#include <mma.h>
#include <cstdint>

using namespace nvcuda;

#define NBATCH 8192
#define SETS   4
#define GRID   (NBATCH/SETS)
#define TPB    512
#define NLAT   16

// ---------------- shared memory layout (bytes) ----------------
#define O_W2HI 0        // bf16 [128][136]  = 34816
#define O_W2LO 34816    // bf16 [128][136]  = 34816
#define O_W3HI 69632    // bf16 [128][40]   = 10240
#define O_W3LO 79872    // bf16 [128][40]   = 10240
#define O_AHI  90112    // A hi bf16 [128][136] = 34816
#define O_ALO  124928   // A lo bf16 [128][136] = 34816
#define O_HT   90112    // fp32 [128][132] = 67584 (aliases A region between layer2/epi1)
#define O_WP   159744   // f32 [32][128] = 16384
#define O_ZC   176128   // f32 [32][132] = 16896
#define O_X    193024   // 2048
#define O_W1   195072   // 2048
#define O_B1   197120   // 512
#define O_B2   197632   // 512
#define O_B3   198144   // 128
#define O_PL   198272   // 128
#define SMEM_BYTES 198400

__device__ __forceinline__ uint32_t pack_bf16x2(float lo, float hi) {
    __nv_bfloat162 t;
    t.x = __float2bfloat16_rn(lo);
    t.y = __float2bfloat16_rn(hi);
    return *(uint32_t*)&t;
}

__global__ __launch_bounds__(TPB, 1)
void enc_kernel(const float* __restrict__ x,  const float* __restrict__ W1,
                const float* __restrict__ b1, const float* __restrict__ W2,
                const float* __restrict__ b2, const float* __restrict__ W3,
                const float* __restrict__ b3, const float* __restrict__ pwm,
                const float* __restrict__ eps, float* __restrict__ out)
{
    extern __shared__ __align__(1024) char smem[];
    const int tid = threadIdx.x;
    const int wid = tid >> 5, lane = tid & 31;

    __nv_bfloat16* sW2hi = (__nv_bfloat16*)(smem + O_W2HI);
    __nv_bfloat16* sW2lo = (__nv_bfloat16*)(smem + O_W2LO);
    __nv_bfloat16* sW3hi = (__nv_bfloat16*)(smem + O_W3HI);
    __nv_bfloat16* sW3lo = (__nv_bfloat16*)(smem + O_W3LO);
    __nv_bfloat16* sAhi  = (__nv_bfloat16*)(smem + O_AHI);
    __nv_bfloat16* sAlo  = (__nv_bfloat16*)(smem + O_ALO);
    float*         sHt   = (float*)(smem + O_HT);
    float*         sWp   = (float*)(smem + O_WP);
    float*         sZc   = (float*)(smem + O_ZC);

    // ---------- stage invariant weights (hi/lo bf16 split, paired) ----------
    {
        const float2* W2v = (const float2*)W2;       // 8192 pairs
        uint32_t* w2hiW = (uint32_t*)sW2hi;
        uint32_t* w2loW = (uint32_t*)sW2lo;
        #pragma unroll 4
        for (int r = 0; r < 16; r++) {
            int idx = tid + r * TPB;
            float2 w = W2v[idx];
            __nv_bfloat16 h0 = __float2bfloat16_rn(w.x);
            __nv_bfloat16 h1 = __float2bfloat16_rn(w.y);
            float r0 = w.x - __bfloat162float(h0);
            float r1 = w.y - __bfloat162float(h1);
            int j = idx >> 6, kp = idx & 63;
            __nv_bfloat162 hp; hp.x = h0; hp.y = h1;
            w2hiW[j*68 + kp] = *(uint32_t*)&hp;
            w2loW[j*68 + kp] = pack_bf16x2(r0, r1);
        }
        const float2* W3v = (const float2*)W3;       // 2048 pairs
        uint32_t* w3hiW = (uint32_t*)sW3hi;
        uint32_t* w3loW = (uint32_t*)sW3lo;
        #pragma unroll
        for (int r = 0; r < 4; r++) {
            int idx = tid + r * TPB;
            float2 w = W3v[idx];
            __nv_bfloat16 h0 = __float2bfloat16_rn(w.x);
            __nv_bfloat16 h1 = __float2bfloat16_rn(w.y);
            float r0 = w.x - __bfloat162float(h0);
            float r1 = w.y - __bfloat162float(h1);
            int k = idx >> 4, cp = idx & 15;
            __nv_bfloat162 hp; hp.x = h0; hp.y = h1;
            w3hiW[k*20 + cp] = *(uint32_t*)&hp;
            w3loW[k*20 + cp] = pack_bf16x2(r0, r1);
        }
        if (tid < 128) ((float4*)(smem + O_W1))[tid] = ((const float4*)W1)[tid];
        if (tid >= 128 && tid < 160) ((float4*)(smem + O_B1))[tid-128] = ((const float4*)b1)[tid-128];
        if (tid >= 160 && tid < 192) ((float4*)(smem + O_B2))[tid-160] = ((const float4*)b2)[tid-160];
        if (tid >= 192 && tid < 200) ((float4*)(smem + O_B3))[tid-192] = ((const float4*)b3)[tid-192];
        for (int i = tid; i < 4096; i += TPB) {
            int c = i >> 7, pp = i & 127;
            float pos = (float)pp / 127.0f * 20.0f;
            int idx = (int)pos; if (idx > 20) idx = 20;
            float frac = pos - (float)idx;
            int idx2 = idx + 1; if (idx2 > 20) idx2 = 20;
            sWp[i] = (1.0f - frac) * pwm[c*21 + idx] + frac * pwm[c*21 + idx2];
        }
    }

    for (int s = 0; s < SETS; s++) {
        const int bset = blockIdx.x * SETS + s;
        __syncthreads();
        if (tid < 128) ((float4*)(smem + O_X))[tid] = ((const float4*)(x + (size_t)bset * 512))[tid];
        __syncthreads();

        // ---------- layer 1 -> A1 hi/lo bf16 [p][j] (paired stores) ----------
        {
            const float* sX  = (const float*)(smem + O_X);
            const float* sW1 = (const float*)(smem + O_W1);
            const float* sb1 = (const float*)(smem + O_B1);
            const int p = tid >> 2, kg = tid & 3;
            const int j0 = kg * 32;
            float x0 = sX[p*4+0], x1 = sX[p*4+1], x2 = sX[p*4+2], x3 = sX[p*4+3];
            uint32_t* hiw = (uint32_t*)sAhi + p*68 + kg*16;
            uint32_t* low = (uint32_t*)sAlo + p*68 + kg*16;
            #pragma unroll 4
            for (int t = 0; t < 16; t++) {
                int j = j0 + 2*t;
                float a0 = sb1[j], a1 = sb1[j+1];
                a0 = fmaf(x0, sW1[j],       a0);  a1 = fmaf(x0, sW1[j+1],       a1);
                a0 = fmaf(x1, sW1[128 + j], a0);  a1 = fmaf(x1, sW1[128 + j+1], a1);
                a0 = fmaf(x2, sW1[256 + j], a0);  a1 = fmaf(x2, sW1[256 + j+1], a1);
                a0 = fmaf(x3, sW1[384 + j], a0);  a1 = fmaf(x3, sW1[384 + j+1], a1);
                a0 = fmaxf(a0, 0.0f);  a1 = fmaxf(a1, 0.0f);
                __nv_bfloat16 h0 = __float2bfloat16_rn(a0);
                __nv_bfloat16 h1 = __float2bfloat16_rn(a1);
                float r0 = a0 - __bfloat162float(h0);
                float r1 = a1 - __bfloat162float(h1);
                __nv_bfloat162 hp; hp.x = h0; hp.y = h1;
                hiw[t] = *(uint32_t*)&hp;
                low[t] = pack_bf16x2(r0, r1);
            }
        }
        __syncthreads();

        // ---------- layer 2: C[128x128] = H1 x W2 (16 warps, 32x32 tiles) ----------
        {
            const int wm = wid >> 2, wn = wid & 3;
            const int m0 = wm * 32, n0 = wn * 32;
            wmma::fragment<wmma::accumulator, 16,16,16, float> c[2][2];
            #pragma unroll
            for (int i = 0; i < 2; i++)
                #pragma unroll
                for (int j = 0; j < 2; j++) wmma::fill_fragment(c[i][j], 0.0f);

            #pragma unroll
            for (int kk = 0; kk < 8; kk++) {
                const int k0 = kk * 16;
                wmma::fragment<wmma::matrix_a, 16,16,16, __nv_bfloat16, wmma::row_major> ahi[2], alo[2];
                wmma::fragment<wmma::matrix_b, 16,16,16, __nv_bfloat16, wmma::row_major> bhi[2], blo[2];
                #pragma unroll
                for (int i = 0; i < 2; i++) {
                    wmma::load_matrix_sync(ahi[i], sAhi + (m0 + 16*i)*136 + k0, 136);
                    wmma::load_matrix_sync(alo[i], sAlo + (m0 + 16*i)*136 + k0, 136);
                }
                #pragma unroll
                for (int j = 0; j < 2; j++) {
                    wmma::load_matrix_sync(bhi[j], sW2hi + k0*136 + n0 + 16*j, 136);
                    wmma::load_matrix_sync(blo[j], sW2lo + k0*136 + n0 + 16*j, 136);
                }
                #pragma unroll
                for (int i = 0; i < 2; i++)
                    #pragma unroll
                    for (int j = 0; j < 2; j++) {
                        wmma::mma_sync(c[i][j], ahi[i], bhi[j], c[i][j]);
                        wmma::mma_sync(c[i][j], ahi[i], blo[j], c[i][j]);
                        wmma::mma_sync(c[i][j], alo[i], bhi[j], c[i][j]);
                    }
            }
            __syncthreads();   // all warps done reading A1 -> safe to overwrite via sHt
            #pragma unroll
            for (int i = 0; i < 2; i++)
                #pragma unroll
                for (int j = 0; j < 2; j++)
                    wmma::store_matrix_sync(sHt + (m0 + 16*i)*132 + n0 + 16*j, c[i][j], 132, wmma::mem_row_major);
        }
        __syncthreads();

        // ---------- epilogue1: h2 = relu(Ht + b2) -> A2 hi/lo (float4 loads, paired stores) ----------
        {
            const float* sb2 = (const float*)(smem + O_B2);
            const int p = tid >> 2, kg = tid & 3;
            const int k0 = kg * 32;
            const float4* hrow = (const float4*)(sHt + p*132 + k0);
            float v[32];
            #pragma unroll
            for (int u = 0; u < 8; u++) {
                float4 f = hrow[u];
                v[4*u+0] = f.x; v[4*u+1] = f.y; v[4*u+2] = f.z; v[4*u+3] = f.w;
            }
            #pragma unroll
            for (int k = 0; k < 32; k++)
                v[k] = fmaxf(v[k] + sb2[k0 + k], 0.0f);
            __syncthreads();   // all reads of Ht done before overwriting with A2
            uint32_t* hiw = (uint32_t*)sAhi + p*68 + kg*16;
            uint32_t* low = (uint32_t*)sAlo + p*68 + kg*16;
            #pragma unroll 4
            for (int t = 0; t < 16; t++) {
                float a0 = v[2*t], a1 = v[2*t+1];
                __nv_bfloat16 h0 = __float2bfloat16_rn(a0);
                __nv_bfloat16 h1 = __float2bfloat16_rn(a1);
                float r0 = a0 - __bfloat162float(h0);
                float r1 = a1 - __bfloat162float(h1);
                __nv_bfloat162 hp; hp.x = h0; hp.y = h1;
                hiw[t] = *(uint32_t*)&hp;
                low[t] = pack_bf16x2(r0, r1);
            }
        }
        __syncthreads();

        // ---------- layer 3: Z[128x32] = H2 x W3 (8 warps, 32x16 tiles) ----------
        if (wid < 8) {
            const int wm = wid >> 1, wn = wid & 1;
            const int m0 = wm * 32, n0 = wn * 16;
            wmma::fragment<wmma::accumulator, 16,16,16, float> c3[2];
            wmma::fill_fragment(c3[0], 0.0f);
            wmma::fill_fragment(c3[1], 0.0f);
            #pragma unroll
            for (int kk = 0; kk < 8; kk++) {
                const int k0 = kk * 16;
                wmma::fragment<wmma::matrix_a, 16,16,16, __nv_bfloat16, wmma::row_major> ahi[2], alo[2];
                wmma::fragment<wmma::matrix_b, 16,16,16, __nv_bfloat16, wmma::row_major> bhi, blo;
                #pragma unroll
                for (int i = 0; i < 2; i++) {
                    wmma::load_matrix_sync(ahi[i], sAhi + (m0 + 16*i)*136 + k0, 136);
                    wmma::load_matrix_sync(alo[i], sAlo + (m0 + 16*i)*136 + k0, 136);
                }
                wmma::load_matrix_sync(bhi, sW3hi + k0*40 + n0, 40);
                wmma::load_matrix_sync(blo, sW3lo + k0*40 + n0, 40);
                #pragma unroll
                for (int i = 0; i < 2; i++) {
                    wmma::mma_sync(c3[i], ahi[i], bhi, c3[i]);
                    wmma::mma_sync(c3[i], ahi[i], blo, c3[i]);
                    wmma::mma_sync(c3[i], alo[i], bhi, c3[i]);
                }
            }
            // store transposed into ZC: element (m,n) -> sZc[(n0+n)*132 + (m0+m)]
            wmma::store_matrix_sync(sZc + n0*132 + m0,      c3[0], 132, wmma::mem_col_major);
            wmma::store_matrix_sync(sZc + n0*132 + m0 + 16, c3[1], 132, wmma::mem_col_major);
        }
        __syncthreads();

        // ---------- bitonic sorted-dot pool (2 channels per warp) ----------
        {
            const float* sb3 = (const float*)(smem + O_B3);
            float* sPl = (float*)(smem + O_PL);
            #pragma unroll
            for (int cc = 0; cc < 2; cc++) {
                const int c = wid * 2 + cc;
                const float bias = sb3[c];
                const float* zp = sZc + c * 132;
                float v[4];
                #pragma unroll
                for (int r = 0; r < 4; r++) v[r] = zp[r*32 + lane] + bias;

                // bitonic sort ascending over 128 values (idx = r*32 + lane)
                #pragma unroll
                for (int k = 2; k <= 128; k <<= 1) {
                    #pragma unroll
                    for (int st = 64; st >= 1; st >>= 1) {
                        if (st >= k) continue;
                        if (st < 32) {
                            const bool lower = ((lane & st) == 0);
                            #pragma unroll
                            for (int r = 0; r < 4; r++) {
                                float o = __shfl_xor_sync(0xffffffffu, v[r], st);
                                bool up = (((r*32 + lane) & k) == 0);
                                bool tmin = (up == lower);
                                float mn = fminf(v[r], o), mx = fmaxf(v[r], o);
                                v[r] = tmin ? mn : mx;
                            }
                        } else if (st == 32) {
                            #pragma unroll
                            for (int ra = 0; ra < 4; ra += 2) {
                                bool up = (((ra*32) & k) == 0);
                                float mn = fminf(v[ra], v[ra+1]), mx = fmaxf(v[ra], v[ra+1]);
                                v[ra]   = up ? mn : mx;
                                v[ra+1] = up ? mx : mn;
                            }
                        } else {    // st == 64 (k == 128, ascending)
                            #pragma unroll
                            for (int ra = 0; ra < 2; ra++) {
                                float mn = fminf(v[ra], v[ra+2]), mx = fmaxf(v[ra], v[ra+2]);
                                v[ra]   = mn;
                                v[ra+2] = mx;
                            }
                        }
                    }
                }

                const float* wc = sWp + c * 128;
                float sum = v[0] * wc[127 - lane]
                          + v[1] * wc[95  - lane]
                          + v[2] * wc[63  - lane]
                          + v[3] * wc[31  - lane];
                #pragma unroll
                for (int ofs = 16; ofs > 0; ofs >>= 1)
                    sum += __shfl_xor_sync(0xffffffffu, sum, ofs);
                if (lane == 0) sPl[c] = sum;
            }
        }
        __syncthreads();

        // ---------- reparameterize + write ----------
        if (tid < NLAT) {
            const float* sPl = (const float*)(smem + O_PL);
            float mu = sPl[2*tid];
            float lv = sPl[2*tid + 1];
            float e  = eps[(size_t)bset*NLAT + tid];
            float smp = fmaf(e, expf(0.5f * lv), mu);
            out[(size_t)bset*NLAT + tid] = mu;
            out[(size_t)(NBATCH*NLAT)   + (size_t)bset*NLAT + tid] = lv;
            out[(size_t)(2*NBATCH*NLAT) + (size_t)bset*NLAT + tid] = smp;
        }
    }
}

extern "C" void kernel_launch(void* const* d_in, const int* in_sizes, int n_in,
                              void* d_out, int out_size) {
    const float* x   = (const float*)d_in[0];
    const float* W1  = (const float*)d_in[1];
    const float* b1  = (const float*)d_in[2];
    const float* W2  = (const float*)d_in[3];
    const float* b2  = (const float*)d_in[4];
    const float* W3  = (const float*)d_in[5];
    const float* b3  = (const float*)d_in[6];
    const float* pwm = (const float*)d_in[7];
    const float* eps = (const float*)d_in[8];
    float* out = (float*)d_out;

    cudaFuncSetAttribute(enc_kernel, cudaFuncAttributeMaxDynamicSharedMemorySize, SMEM_BYTES);
    enc_kernel<<<GRID, TPB, SMEM_BYTES>>>(x, W1, b1, W2, b2, W3, b3, pwm, eps, out);
}

// round 11
// speedup vs baseline: 2.8920x; 1.4114x over previous
#include <cuda_runtime.h>
#include <cuda_bf16.h>
#include <cstdint>

#define NBATCH 8192
#define SETS   4
#define GRID   (NBATCH/SETS)
#define TPB    512
#define NLAT   16

#define SA 136            // halfword stride for [.][k] bf16 arrays
#define PLANE_A  34816    // 128*136*2 bytes
#define PLANE_W2 34816
#define PLANE_W3 8704     // 32*136*2

// ---------------- shared memory layout (bytes) ----------------
#define O_W2B 0           // W2 as B: [n=128][k=136] bf16, hi+lo planes (69632)
#define O_W3B 69632       // W3 as B: [n=32][k=136] bf16, hi+lo planes (17408)
#define O_A1  87040       // A: [m=128][k=136] bf16, hi+lo planes (69632)
#define O_ZP  87040       // alias: Zpart[4][32][132] f32 = 67584
#define O_WP  156672      // fspool weights f32 [32][128] (16384)
#define O_X   173056      // 2048
#define O_W1  175104      // 2048
#define O_B1  177152      // 512
#define O_B2  177664      // 512
#define O_B3  178176      // 128
#define O_PL  178304      // 128
#define SMEM_BYTES 178432

__device__ __forceinline__ uint32_t cvta_smem(const void* p) {
    uint32_t a;
    asm("{ .reg .u64 t; cvta.to.shared.u64 t, %1; cvt.u32.u64 %0, t; }" : "=r"(a) : "l"(p));
    return a;
}
__device__ __forceinline__ uint32_t pack_bf16x2(float lo, float hi) {
    __nv_bfloat162 t;
    t.x = __float2bfloat16_rn(lo);
    t.y = __float2bfloat16_rn(hi);
    return *(uint32_t*)&t;
}

#define LDSM4(R0,R1,R2,R3,ADDR) \
    asm volatile("ldmatrix.sync.aligned.m8n8.x4.shared.b16 {%0,%1,%2,%3}, [%4];" \
        : "=r"(R0),"=r"(R1),"=r"(R2),"=r"(R3) : "r"(ADDR) : "memory")

#define MMA(C,A,B) \
    asm volatile("mma.sync.aligned.m16n8k16.row.col.f32.bf16.bf16.f32 " \
        "{%0,%1,%2,%3}, {%4,%5,%6,%7}, {%8,%9}, {%0,%1,%2,%3};" \
        : "+f"((C)[0]),"+f"((C)[1]),"+f"((C)[2]),"+f"((C)[3]) \
        : "r"((A)[0]),"r"((A)[1]),"r"((A)[2]),"r"((A)[3]), "r"((B)[0]),"r"((B)[1]))

__global__ __launch_bounds__(TPB, 1)
void enc_kernel(const float* __restrict__ x,  const float* __restrict__ W1,
                const float* __restrict__ b1, const float* __restrict__ W2,
                const float* __restrict__ b2, const float* __restrict__ W3,
                const float* __restrict__ b3, const float* __restrict__ pwm,
                const float* __restrict__ eps, float* __restrict__ out)
{
    extern __shared__ __align__(1024) char smem[];
    const uint32_t sb = cvta_smem(smem);
    const int tid = threadIdx.x;
    const int wid = tid >> 5, lane = tid & 31;
    const int g = lane >> 2, t4 = lane & 3;
    const int l8 = lane & 7, mi = lane >> 3;

    __nv_bfloat16* sW2B = (__nv_bfloat16*)(smem + O_W2B);
    __nv_bfloat16* sW3B = (__nv_bfloat16*)(smem + O_W3B);
    float* sWp = (float*)(smem + O_WP);

    // ---------- stage invariant weights: hi/lo bf16, transposed to [n][k] ----------
    {
        #pragma unroll 4
        for (int r = 0; r < 32; r++) {
            int i = tid + r * TPB;               // i = j*128 + n  (j = k-dim, n = out)
            float v = W2[i];
            __nv_bfloat16 hi = __float2bfloat16_rn(v);
            __nv_bfloat16 lo = __float2bfloat16_rn(v - __bfloat162float(hi));
            int j = i >> 7, n = i & 127;
            sW2B[n*SA + j] = hi;
            sW2B[PLANE_W2/2 + n*SA + j] = lo;
        }
        #pragma unroll
        for (int r = 0; r < 8; r++) {
            int i = tid + r * TPB;               // i = k*32 + c
            float v = W3[i];
            __nv_bfloat16 hi = __float2bfloat16_rn(v);
            __nv_bfloat16 lo = __float2bfloat16_rn(v - __bfloat162float(hi));
            int k = i >> 5, c = i & 31;
            sW3B[c*SA + k] = hi;
            sW3B[PLANE_W3/2 + c*SA + k] = lo;
        }
        if (tid < 128) ((float4*)(smem + O_W1))[tid] = ((const float4*)W1)[tid];
        if (tid >= 128 && tid < 160) ((float4*)(smem + O_B1))[tid-128] = ((const float4*)b1)[tid-128];
        if (tid >= 160 && tid < 192) ((float4*)(smem + O_B2))[tid-160] = ((const float4*)b2)[tid-160];
        if (tid >= 192 && tid < 200) ((float4*)(smem + O_B3))[tid-192] = ((const float4*)b3)[tid-192];
        for (int i = tid; i < 4096; i += TPB) {
            int c = i >> 7, pp = i & 127;
            float pos = (float)pp / 127.0f * 20.0f;
            int idx = (int)pos; if (idx > 20) idx = 20;
            float frac = pos - (float)idx;
            int idx2 = idx + 1; if (idx2 > 20) idx2 = 20;
            sWp[i] = (1.0f - frac) * pwm[c*21 + idx] + frac * pwm[c*21 + idx2];
        }
    }
    __syncthreads();

    const int wm = wid >> 2, wn = wid & 3;
    const int m0 = wm * 32, n0 = wn * 32;

    // ldmatrix per-lane geometry
    const int aRow = (mi & 1) * 8 + l8;          // A: mi0/2 -> rows 0-7, mi1/3 -> rows 8-15
    const int aCol = (mi >> 1) * 8;              //    mi0/1 -> k+0,     mi2/3 -> k+8
    const int bRow = ((mi >> 1) & 1) * 8 + l8;   // B: mi0/1 -> rows 0-7, mi2/3 -> rows 8-15
    const int bCol = (mi & 1) * 8;               //    mi0/2 -> k+0,     mi1/3 -> k+8

    // ---------- persistent W3 B-fragments (this warp's layer3 k-slice = [n0, n0+32)) ----------
    uint32_t b3h[2][4][2], b3l[2][4][2];         // [kf][chf][reg]
    {
        #pragma unroll
        for (int kf = 0; kf < 2; kf++) {
            #pragma unroll
            for (int cp = 0; cp < 2; cp++) {     // chf pairs {0,1},{2,3}
                uint32_t addrh = sb + O_W3B + (uint32_t)((cp*16 + bRow)*SA + n0 + kf*16 + bCol)*2;
                uint32_t r0,r1,r2,r3;
                LDSM4(r0,r1,r2,r3, addrh);
                b3h[kf][2*cp][0]=r0; b3h[kf][2*cp][1]=r1; b3h[kf][2*cp+1][0]=r2; b3h[kf][2*cp+1][1]=r3;
                LDSM4(r0,r1,r2,r3, addrh + PLANE_W3);
                b3l[kf][2*cp][0]=r0; b3l[kf][2*cp][1]=r1; b3l[kf][2*cp+1][0]=r2; b3l[kf][2*cp+1][1]=r3;
            }
        }
    }

    for (int s = 0; s < SETS; s++) {
        const int bset = blockIdx.x * SETS + s;
        if (tid < 128) ((float4*)(smem + O_X))[tid] = ((const float4*)(x + (size_t)bset * 512))[tid];
        __syncthreads();   // X ready; prev set's Zpart reads + sPl reads done

        // ---------- layer 1 -> A1 hi/lo bf16 [p][j], stride SA ----------
        {
            const float* sX  = (const float*)(smem + O_X);
            const float* sW1 = (const float*)(smem + O_W1);
            const float* sb1 = (const float*)(smem + O_B1);
            const int p = tid >> 2, kg = tid & 3;
            const int j0 = kg * 32;
            float x0 = sX[p*4+0], x1 = sX[p*4+1], x2 = sX[p*4+2], x3 = sX[p*4+3];
            uint32_t* hiw = (uint32_t*)(smem + O_A1) + p*(SA/2) + kg*16;
            uint32_t* low = (uint32_t*)(smem + O_A1 + PLANE_A) + p*(SA/2) + kg*16;
            #pragma unroll 4
            for (int tt = 0; tt < 16; tt++) {
                int j = j0 + 2*tt;
                float a0 = sb1[j], a1 = sb1[j+1];
                a0 = fmaf(x0, sW1[j],       a0);  a1 = fmaf(x0, sW1[j+1],       a1);
                a0 = fmaf(x1, sW1[128 + j], a0);  a1 = fmaf(x1, sW1[128 + j+1], a1);
                a0 = fmaf(x2, sW1[256 + j], a0);  a1 = fmaf(x2, sW1[256 + j+1], a1);
                a0 = fmaf(x3, sW1[384 + j], a0);  a1 = fmaf(x3, sW1[384 + j+1], a1);
                a0 = fmaxf(a0, 0.0f);  a1 = fmaxf(a1, 0.0f);
                __nv_bfloat16 h0 = __float2bfloat16_rn(a0);
                __nv_bfloat16 h1 = __float2bfloat16_rn(a1);
                __nv_bfloat162 hp; hp.x = h0; hp.y = h1;
                hiw[tt] = *(uint32_t*)&hp;
                low[tt] = pack_bf16x2(a0 - __bfloat162float(h0), a1 - __bfloat162float(h1));
            }
        }
        __syncthreads();

        // ---------- layer 2: C[32x32] per warp via mma.sync, 8 k-steps ----------
        float cacc[2][4][4];
        #pragma unroll
        for (int i = 0; i < 2; i++)
            #pragma unroll
            for (int j = 0; j < 4; j++)
                #pragma unroll
                for (int r = 0; r < 4; r++) cacc[i][j][r] = 0.0f;
        {
            uint32_t aAddr[2][2], bAddr[2][2];   // [plane][mf] / [plane][npair]
            #pragma unroll
            for (int pl = 0; pl < 2; pl++) {
                #pragma unroll
                for (int mf = 0; mf < 2; mf++)
                    aAddr[pl][mf] = sb + O_A1 + pl*PLANE_A
                                  + (uint32_t)((m0 + 16*mf + aRow)*SA + aCol)*2;
                #pragma unroll
                for (int np = 0; np < 2; np++)
                    bAddr[pl][np] = sb + O_W2B + pl*PLANE_W2
                                  + (uint32_t)((n0 + np*16 + bRow)*SA + bCol)*2;
            }
            #pragma unroll
            for (int kk = 0; kk < 8; kk++) {
                uint32_t af[2][2][4];            // [plane][mf][reg]
                #pragma unroll
                for (int pl = 0; pl < 2; pl++)
                    #pragma unroll
                    for (int mf = 0; mf < 2; mf++)
                        LDSM4(af[pl][mf][0], af[pl][mf][1], af[pl][mf][2], af[pl][mf][3],
                              aAddr[pl][mf] + kk*32);
                uint32_t bfr[2][4][2];           // [plane][nf][reg]
                #pragma unroll
                for (int pl = 0; pl < 2; pl++)
                    #pragma unroll
                    for (int np = 0; np < 2; np++) {
                        uint32_t r0,r1,r2,r3;
                        LDSM4(r0,r1,r2,r3, bAddr[pl][np] + kk*32);
                        bfr[pl][2*np][0]=r0; bfr[pl][2*np][1]=r1;
                        bfr[pl][2*np+1][0]=r2; bfr[pl][2*np+1][1]=r3;
                    }
                #pragma unroll
                for (int mf = 0; mf < 2; mf++)
                    #pragma unroll
                    for (int nf = 0; nf < 4; nf++) {
                        MMA(cacc[mf][nf], af[0][mf], bfr[0][nf]);   // hi*hi
                        MMA(cacc[mf][nf], af[0][mf], bfr[1][nf]);   // hi*lo
                        MMA(cacc[mf][nf], af[1][mf], bfr[0][nf]);   // lo*hi
                    }
            }
        }

        // ---------- epilogue in registers: bias + relu + hi/lo split -> layer3 A frags ----------
        uint32_t Ah[2][2][4], Al[2][2][4];       // [mf][kf][reg]
        {
            const float* sb2 = (const float*)(smem + O_B2);
            #pragma unroll
            for (int nf = 0; nf < 4; nf++) {
                float bv0 = sb2[n0 + 8*nf + 2*t4];
                float bv1 = sb2[n0 + 8*nf + 2*t4 + 1];
                #pragma unroll
                for (int mf = 0; mf < 2; mf++) {
                    cacc[mf][nf][0] = fmaxf(cacc[mf][nf][0] + bv0, 0.0f);
                    cacc[mf][nf][1] = fmaxf(cacc[mf][nf][1] + bv1, 0.0f);
                    cacc[mf][nf][2] = fmaxf(cacc[mf][nf][2] + bv0, 0.0f);
                    cacc[mf][nf][3] = fmaxf(cacc[mf][nf][3] + bv1, 0.0f);
                }
            }
            #pragma unroll
            for (int mf = 0; mf < 2; mf++)
                #pragma unroll
                for (int kf = 0; kf < 2; kf++) {
                    const float* cL = cacc[mf][2*kf];      // cols 2t,2t+1 (k-offset 0..7)
                    const float* cH = cacc[mf][2*kf+1];    // cols 8+2t    (k-offset 8..15)
                    #pragma unroll
                    for (int h = 0; h < 2; h++) {          // h=0: rows g, h=1: rows g+8
                        float v0 = cL[2*h], v1 = cL[2*h+1];
                        float w0 = cH[2*h], w1 = cH[2*h+1];
                        __nv_bfloat16 b0 = __float2bfloat16_rn(v0);
                        __nv_bfloat16 b1 = __float2bfloat16_rn(v1);
                        __nv_bfloat16 b2_ = __float2bfloat16_rn(w0);
                        __nv_bfloat16 b3_ = __float2bfloat16_rn(w1);
                        __nv_bfloat162 p0; p0.x = b0; p0.y = b1;
                        __nv_bfloat162 p1; p1.x = b2_; p1.y = b3_;
                        Ah[mf][kf][h]   = *(uint32_t*)&p0;
                        Ah[mf][kf][2+h] = *(uint32_t*)&p1;
                        Al[mf][kf][h]   = pack_bf16x2(v0 - __bfloat162float(b0),
                                                      v1 - __bfloat162float(b1));
                        Al[mf][kf][2+h] = pack_bf16x2(w0 - __bfloat162float(b2_),
                                                      w1 - __bfloat162float(b3_));
                    }
                }
        }

        // ---------- layer 3: partial Z[32m x 32ch] over this warp's k-slice ----------
        float zacc[2][4][4];
        #pragma unroll
        for (int i = 0; i < 2; i++)
            #pragma unroll
            for (int j = 0; j < 4; j++)
                #pragma unroll
                for (int r = 0; r < 4; r++) zacc[i][j][r] = 0.0f;
        #pragma unroll
        for (int mf = 0; mf < 2; mf++)
            #pragma unroll
            for (int chf = 0; chf < 4; chf++)
                #pragma unroll
                for (int kf = 0; kf < 2; kf++) {
                    MMA(zacc[mf][chf], Ah[mf][kf], b3h[kf][chf]);
                    MMA(zacc[mf][chf], Ah[mf][kf], b3l[kf][chf]);
                    MMA(zacc[mf][chf], Al[mf][kf], b3h[kf][chf]);
                }

        __syncthreads();   // all warps done reading A1/W2 via ldmatrix -> Zpart may alias A1

        // ---------- store partial Z: Zpart[wn][ch][132] ----------
        {
            float* zp = (float*)(smem + O_ZP) + wn * 4224;
            #pragma unroll
            for (int mf = 0; mf < 2; mf++)
                #pragma unroll
                for (int chf = 0; chf < 4; chf++) {
                    int ch = 8*chf + 2*t4;
                    int m  = m0 + 16*mf + g;
                    zp[ch*132 + m]         = zacc[mf][chf][0];
                    zp[(ch+1)*132 + m]     = zacc[mf][chf][1];
                    zp[ch*132 + m + 8]     = zacc[mf][chf][2];
                    zp[(ch+1)*132 + m + 8] = zacc[mf][chf][3];
                }
        }
        __syncthreads();

        // ---------- bitonic sorted-dot pool (2 channels per warp) ----------
        {
            const float* sb3 = (const float*)(smem + O_B3);
            const float* zp0 = (const float*)(smem + O_ZP);
            float* sPl = (float*)(smem + O_PL);
            #pragma unroll
            for (int cc = 0; cc < 2; cc++) {
                const int c = wid * 2 + cc;
                const float bias = sb3[c];
                float v[4];
                #pragma unroll
                for (int r = 0; r < 4; r++) {
                    int p = r*32 + lane;
                    v[r] = zp0[c*132 + p] + zp0[4224 + c*132 + p]
                         + zp0[8448 + c*132 + p] + zp0[12672 + c*132 + p] + bias;
                }
                // bitonic sort ascending over 128 values (idx = r*32 + lane)
                #pragma unroll
                for (int k = 2; k <= 128; k <<= 1) {
                    #pragma unroll
                    for (int st = 64; st >= 1; st >>= 1) {
                        if (st >= k) continue;
                        if (st < 32) {
                            const bool lower = ((lane & st) == 0);
                            #pragma unroll
                            for (int r = 0; r < 4; r++) {
                                float o = __shfl_xor_sync(0xffffffffu, v[r], st);
                                bool up = (((r*32 + lane) & k) == 0);
                                bool tmin = (up == lower);
                                float mn = fminf(v[r], o), mx = fmaxf(v[r], o);
                                v[r] = tmin ? mn : mx;
                            }
                        } else if (st == 32) {
                            #pragma unroll
                            for (int ra = 0; ra < 4; ra += 2) {
                                bool up = (((ra*32) & k) == 0);
                                float mn = fminf(v[ra], v[ra+1]), mx = fmaxf(v[ra], v[ra+1]);
                                v[ra]   = up ? mn : mx;
                                v[ra+1] = up ? mx : mn;
                            }
                        } else {
                            #pragma unroll
                            for (int ra = 0; ra < 2; ra++) {
                                float mn = fminf(v[ra], v[ra+2]), mx = fmaxf(v[ra], v[ra+2]);
                                v[ra]   = mn;
                                v[ra+2] = mx;
                            }
                        }
                    }
                }
                const float* wc = sWp + c * 128;
                float sum = v[0] * wc[127 - lane]
                          + v[1] * wc[95  - lane]
                          + v[2] * wc[63  - lane]
                          + v[3] * wc[31  - lane];
                #pragma unroll
                for (int ofs = 16; ofs > 0; ofs >>= 1)
                    sum += __shfl_xor_sync(0xffffffffu, sum, ofs);
                if (lane == 0) sPl[c] = sum;
            }
        }
        __syncthreads();

        // ---------- reparameterize + write ----------
        if (tid < NLAT) {
            const float* sPl = (const float*)(smem + O_PL);
            float mu = sPl[2*tid];
            float lv = sPl[2*tid + 1];
            float e  = eps[(size_t)bset*NLAT + tid];
            float smp = fmaf(e, expf(0.5f * lv), mu);
            out[(size_t)bset*NLAT + tid] = mu;
            out[(size_t)(NBATCH*NLAT)   + (size_t)bset*NLAT + tid] = lv;
            out[(size_t)(2*NBATCH*NLAT) + (size_t)bset*NLAT + tid] = smp;
        }
        __syncthreads();   // sPl reads done; Zpart reads done before next layer1 aliases it
    }
}

extern "C" void kernel_launch(void* const* d_in, const int* in_sizes, int n_in,
                              void* d_out, int out_size) {
    const float* x   = (const float*)d_in[0];
    const float* W1  = (const float*)d_in[1];
    const float* b1  = (const float*)d_in[2];
    const float* W2  = (const float*)d_in[3];
    const float* b2  = (const float*)d_in[4];
    const float* W3  = (const float*)d_in[5];
    const float* b3  = (const float*)d_in[6];
    const float* pwm = (const float*)d_in[7];
    const float* eps = (const float*)d_in[8];
    float* out = (float*)d_out;

    cudaFuncSetAttribute(enc_kernel, cudaFuncAttributeMaxDynamicSharedMemorySize, SMEM_BYTES);
    enc_kernel<<<GRID, TPB, SMEM_BYTES>>>(x, W1, b1, W2, b2, W3, b3, pwm, eps, out);
}

// round 12
// speedup vs baseline: 2.9062x; 1.0049x over previous
#include <cuda_runtime.h>
#include <cuda_bf16.h>
#include <cstdint>

#define NBATCH 8192
#define SETS   4
#define GRID   (NBATCH/SETS)
#define TPB    512
#define NLAT   16

#define SA 136            // halfword stride for A1/W2/W3 [.][k] bf16 arrays
#define PLANE_A  34816    // 128*136*2 bytes
#define PLANE_W2 34816
#define PLANE_W3 8704     // 32*136*2
#define PLANE_X  6144     // 128*24*2

// ---------------- shared memory layout (bytes) ----------------
#define O_W2B 0           // W2 as B: [n=128][k=136] bf16, hi+lo planes (69632)
#define O_W3B 69632       // W3 as B: [n=32][k=136] bf16, hi+lo planes (17408)
#define O_A1  87040       // A: [m=128][k=136] bf16, hi+lo planes (69632)
#define O_ZP  87040       // alias: Zpart[4][32][132] f32 = 67584
#define O_WP  156672      // fspool weights f32 [32][128] (16384)
#define O_XS  173056      // X bf16 [128][24] hi+lo planes (12288)
#define O_W1B 185344      // [W1T|b1] bf16 [128][24] hi+lo planes (12288)
#define O_B2  197632      // 512
#define O_B3  198144      // 128
#define O_PL  198272      // 128
#define SMEM_BYTES 198400

__device__ __forceinline__ uint32_t cvta_smem(const void* p) {
    uint32_t a;
    asm("{ .reg .u64 t; cvta.to.shared.u64 t, %1; cvt.u32.u64 %0, t; }" : "=r"(a) : "l"(p));
    return a;
}
__device__ __forceinline__ uint32_t pack_bf16x2(float lo, float hi) {
    __nv_bfloat162 t;
    t.x = __float2bfloat16_rn(lo);
    t.y = __float2bfloat16_rn(hi);
    return *(uint32_t*)&t;
}

#define LDSM4(R0,R1,R2,R3,ADDR) \
    asm volatile("ldmatrix.sync.aligned.m8n8.x4.shared.b16 {%0,%1,%2,%3}, [%4];" \
        : "=r"(R0),"=r"(R1),"=r"(R2),"=r"(R3) : "r"(ADDR) : "memory")

#define MMA(C,A,B) \
    asm volatile("mma.sync.aligned.m16n8k16.row.col.f32.bf16.bf16.f32 " \
        "{%0,%1,%2,%3}, {%4,%5,%6,%7}, {%8,%9}, {%0,%1,%2,%3};" \
        : "+f"((C)[0]),"+f"((C)[1]),"+f"((C)[2]),"+f"((C)[3]) \
        : "r"((A)[0]),"r"((A)[1]),"r"((A)[2]),"r"((A)[3]), "r"((B)[0]),"r"((B)[1]))

__global__ __launch_bounds__(TPB, 1)
void enc_kernel(const float* __restrict__ x,  const float* __restrict__ W1,
                const float* __restrict__ b1, const float* __restrict__ W2,
                const float* __restrict__ b2, const float* __restrict__ W3,
                const float* __restrict__ b3, const float* __restrict__ pwm,
                const float* __restrict__ eps, float* __restrict__ out)
{
    extern __shared__ __align__(1024) char smem[];
    const uint32_t sb = cvta_smem(smem);
    const int tid = threadIdx.x;
    const int wid = tid >> 5, lane = tid & 31;
    const int g = lane >> 2, t4 = lane & 3;
    const int l8 = lane & 7, mi = lane >> 3;

    __nv_bfloat16* sW2B = (__nv_bfloat16*)(smem + O_W2B);
    __nv_bfloat16* sW3B = (__nv_bfloat16*)(smem + O_W3B);
    float* sWp = (float*)(smem + O_WP);

    // ---------- stage invariant weights: hi/lo bf16, transposed to [n][k] ----------
    {
        #pragma unroll 4
        for (int r = 0; r < 32; r++) {
            int i = tid + r * TPB;               // i = j*128 + n
            float v = W2[i];
            __nv_bfloat16 hi = __float2bfloat16_rn(v);
            __nv_bfloat16 lo = __float2bfloat16_rn(v - __bfloat162float(hi));
            int j = i >> 7, n = i & 127;
            sW2B[n*SA + j] = hi;
            sW2B[PLANE_W2/2 + n*SA + j] = lo;
        }
        #pragma unroll
        for (int r = 0; r < 8; r++) {
            int i = tid + r * TPB;               // i = k*32 + c
            float v = W3[i];
            __nv_bfloat16 hi = __float2bfloat16_rn(v);
            __nv_bfloat16 lo = __float2bfloat16_rn(v - __bfloat162float(hi));
            int k = i >> 5, c = i & 31;
            sW3B[c*SA + k] = hi;
            sW3B[PLANE_W3/2 + c*SA + k] = lo;
        }
        // W1B: row j, cols 0..3 = W1[f][j], col 4 = b1[j], cols 5..23 = 0. Also zero XS rows.
        if (tid < 128) {
            int j = tid;
            uint32_t* wh = (uint32_t*)(smem + O_W1B) + j*12;
            uint32_t* wl = (uint32_t*)(smem + O_W1B + PLANE_X) + j*12;
            uint32_t* xh = (uint32_t*)(smem + O_XS)  + j*12;
            uint32_t* xl = (uint32_t*)(smem + O_XS + PLANE_X) + j*12;
            #pragma unroll
            for (int q = 0; q < 12; q++) { wh[q] = 0u; wl[q] = 0u; xh[q] = 0u; xl[q] = 0u; }
            float w0 = W1[j], w1 = W1[128 + j], w2_ = W1[256 + j], w3_ = W1[384 + j];
            float bb = b1[j];
            __nv_bfloat16 h0 = __float2bfloat16_rn(w0), h1 = __float2bfloat16_rn(w1);
            __nv_bfloat16 h2 = __float2bfloat16_rn(w2_), h3 = __float2bfloat16_rn(w3_);
            __nv_bfloat16 hb = __float2bfloat16_rn(bb);
            __nv_bfloat162 p01; p01.x = h0; p01.y = h1;
            __nv_bfloat162 p23; p23.x = h2; p23.y = h3;
            __nv_bfloat162 pb;  pb.x  = hb; pb.y  = __float2bfloat16_rn(0.0f);
            wh[0] = *(uint32_t*)&p01;
            wh[1] = *(uint32_t*)&p23;
            wh[2] = *(uint32_t*)&pb;
            wl[0] = pack_bf16x2(w0 - __bfloat162float(h0), w1 - __bfloat162float(h1));
            wl[1] = pack_bf16x2(w2_ - __bfloat162float(h2), w3_ - __bfloat162float(h3));
            wl[2] = pack_bf16x2(bb - __bfloat162float(hb), 0.0f);
        }
        if (tid >= 160 && tid < 192) ((float4*)(smem + O_B2))[tid-160] = ((const float4*)b2)[tid-160];
        if (tid >= 192 && tid < 200) ((float4*)(smem + O_B3))[tid-192] = ((const float4*)b3)[tid-192];
        for (int i = tid; i < 4096; i += TPB) {
            int c = i >> 7, pp = i & 127;
            float pos = (float)pp / 127.0f * 20.0f;
            int idx = (int)pos; if (idx > 20) idx = 20;
            float frac = pos - (float)idx;
            int idx2 = idx + 1; if (idx2 > 20) idx2 = 20;
            sWp[i] = (1.0f - frac) * pwm[c*21 + idx] + frac * pwm[c*21 + idx2];
        }
    }
    __syncthreads();

    const int wm = wid >> 2, wn = wid & 3;
    const int m0 = wm * 32, n0 = wn * 32;

    // ldmatrix per-lane geometry (verified by R11 pass)
    const int aRow = (mi & 1) * 8 + l8;
    const int aCol = (mi >> 1) * 8;
    const int bRow = ((mi >> 1) & 1) * 8 + l8;
    const int bCol = (mi & 1) * 8;

    // ---------- persistent W3 B-fragments (this warp's layer3 k-slice = [n0, n0+32)) ----------
    uint32_t b3h[2][4][2], b3l[2][4][2];         // [kf][chf][reg]
    {
        #pragma unroll
        for (int kf = 0; kf < 2; kf++) {
            #pragma unroll
            for (int cp = 0; cp < 2; cp++) {
                uint32_t addrh = sb + O_W3B + (uint32_t)((cp*16 + bRow)*SA + n0 + kf*16 + bCol)*2;
                uint32_t r0,r1,r2,r3;
                LDSM4(r0,r1,r2,r3, addrh);
                b3h[kf][2*cp][0]=r0; b3h[kf][2*cp][1]=r1; b3h[kf][2*cp+1][0]=r2; b3h[kf][2*cp+1][1]=r3;
                LDSM4(r0,r1,r2,r3, addrh + PLANE_W3);
                b3l[kf][2*cp][0]=r0; b3l[kf][2*cp][1]=r1; b3l[kf][2*cp+1][0]=r2; b3l[kf][2*cp+1][1]=r3;
            }
        }
    }

    for (int s = 0; s < SETS; s++) {
        const int bset = blockIdx.x * SETS + s;

        // ---------- stage X (hi/lo bf16, with constant-1 bias column) ----------
        if (tid < 128) {
            float4 xv = ((const float4*)(x + (size_t)bset * 512))[tid];
            uint32_t* xh = (uint32_t*)(smem + O_XS) + tid*12;
            uint32_t* xl = (uint32_t*)(smem + O_XS + PLANE_X) + tid*12;
            __nv_bfloat16 h0 = __float2bfloat16_rn(xv.x), h1 = __float2bfloat16_rn(xv.y);
            __nv_bfloat16 h2 = __float2bfloat16_rn(xv.z), h3 = __float2bfloat16_rn(xv.w);
            __nv_bfloat162 p01; p01.x = h0; p01.y = h1;
            __nv_bfloat162 p23; p23.x = h2; p23.y = h3;
            __nv_bfloat162 pb;  pb.x  = __float2bfloat16_rn(1.0f); pb.y = __float2bfloat16_rn(0.0f);
            xh[0] = *(uint32_t*)&p01;
            xh[1] = *(uint32_t*)&p23;
            xh[2] = *(uint32_t*)&pb;
            xl[0] = pack_bf16x2(xv.x - __bfloat162float(h0), xv.y - __bfloat162float(h1));
            xl[1] = pack_bf16x2(xv.z - __bfloat162float(h2), xv.w - __bfloat162float(h3));
            xl[2] = 0u;
        }
        __syncthreads();   // X ready; prev set's Zpart + sPl reads done

        // ---------- layer 1 via mma: H1 tile [32m x 32j] per warp, k=16 ----------
        {
            // W1 B-fragments (reload per set: 4 LDSM4, negligible)
            uint32_t w1h[4][2], w1l[4][2];
            #pragma unroll
            for (int np = 0; np < 2; np++) {
                uint32_t addrh = sb + O_W1B + (uint32_t)((n0 + np*16 + bRow)*24 + bCol)*2;
                uint32_t r0,r1,r2,r3;
                LDSM4(r0,r1,r2,r3, addrh);
                w1h[2*np][0]=r0; w1h[2*np][1]=r1; w1h[2*np+1][0]=r2; w1h[2*np+1][1]=r3;
                LDSM4(r0,r1,r2,r3, addrh + PLANE_X);
                w1l[2*np][0]=r0; w1l[2*np][1]=r1; w1l[2*np+1][0]=r2; w1l[2*np+1][1]=r3;
            }
            // X A-fragments
            uint32_t xfh[2][4], xfl[2][4];
            #pragma unroll
            for (int mf = 0; mf < 2; mf++) {
                uint32_t ah = sb + O_XS + (uint32_t)((m0 + 16*mf + aRow)*24 + aCol)*2;
                LDSM4(xfh[mf][0], xfh[mf][1], xfh[mf][2], xfh[mf][3], ah);
                LDSM4(xfl[mf][0], xfl[mf][1], xfl[mf][2], xfl[mf][3], ah + PLANE_X);
            }
            float c1[2][4][4];
            #pragma unroll
            for (int i = 0; i < 2; i++)
                #pragma unroll
                for (int j = 0; j < 4; j++)
                    #pragma unroll
                    for (int r = 0; r < 4; r++) c1[i][j][r] = 0.0f;
            #pragma unroll
            for (int mf = 0; mf < 2; mf++)
                #pragma unroll
                for (int nf = 0; nf < 4; nf++) {
                    MMA(c1[mf][nf], xfh[mf], w1h[nf]);
                    MMA(c1[mf][nf], xfh[mf], w1l[nf]);
                    MMA(c1[mf][nf], xfl[mf], w1h[nf]);
                }
            // relu + hi/lo split -> store to A1 (conflict-free paired stores)
            uint32_t* a1h = (uint32_t*)(smem + O_A1);
            uint32_t* a1l = (uint32_t*)(smem + O_A1 + PLANE_A);
            #pragma unroll
            for (int mf = 0; mf < 2; mf++)
                #pragma unroll
                for (int nf = 0; nf < 4; nf++) {
                    #pragma unroll
                    for (int h = 0; h < 2; h++) {
                        float v0 = fmaxf(c1[mf][nf][2*h],   0.0f);
                        float v1 = fmaxf(c1[mf][nf][2*h+1], 0.0f);
                        __nv_bfloat16 bh0 = __float2bfloat16_rn(v0);
                        __nv_bfloat16 bh1 = __float2bfloat16_rn(v1);
                        __nv_bfloat162 ph; ph.x = bh0; ph.y = bh1;
                        int m = m0 + 16*mf + g + 8*h;
                        int w = m*(SA/2) + (n0 >> 1) + 4*nf + t4;
                        a1h[w] = *(uint32_t*)&ph;
                        a1l[w] = pack_bf16x2(v0 - __bfloat162float(bh0),
                                             v1 - __bfloat162float(bh1));
                    }
                }
        }
        __syncthreads();

        // ---------- layer 2: C[32x32] per warp via mma.sync, 8 k-steps ----------
        float cacc[2][4][4];
        #pragma unroll
        for (int i = 0; i < 2; i++)
            #pragma unroll
            for (int j = 0; j < 4; j++)
                #pragma unroll
                for (int r = 0; r < 4; r++) cacc[i][j][r] = 0.0f;
        {
            uint32_t aAddr[2][2], bAddr[2][2];
            #pragma unroll
            for (int pl = 0; pl < 2; pl++) {
                #pragma unroll
                for (int mf = 0; mf < 2; mf++)
                    aAddr[pl][mf] = sb + O_A1 + pl*PLANE_A
                                  + (uint32_t)((m0 + 16*mf + aRow)*SA + aCol)*2;
                #pragma unroll
                for (int np = 0; np < 2; np++)
                    bAddr[pl][np] = sb + O_W2B + pl*PLANE_W2
                                  + (uint32_t)((n0 + np*16 + bRow)*SA + bCol)*2;
            }
            #pragma unroll
            for (int kk = 0; kk < 8; kk++) {
                uint32_t af[2][2][4];
                #pragma unroll
                for (int pl = 0; pl < 2; pl++)
                    #pragma unroll
                    for (int mf = 0; mf < 2; mf++)
                        LDSM4(af[pl][mf][0], af[pl][mf][1], af[pl][mf][2], af[pl][mf][3],
                              aAddr[pl][mf] + kk*32);
                uint32_t bfr[2][4][2];
                #pragma unroll
                for (int pl = 0; pl < 2; pl++)
                    #pragma unroll
                    for (int np = 0; np < 2; np++) {
                        uint32_t r0,r1,r2,r3;
                        LDSM4(r0,r1,r2,r3, bAddr[pl][np] + kk*32);
                        bfr[pl][2*np][0]=r0; bfr[pl][2*np][1]=r1;
                        bfr[pl][2*np+1][0]=r2; bfr[pl][2*np+1][1]=r3;
                    }
                #pragma unroll
                for (int mf = 0; mf < 2; mf++)
                    #pragma unroll
                    for (int nf = 0; nf < 4; nf++) {
                        MMA(cacc[mf][nf], af[0][mf], bfr[0][nf]);   // hi*hi
                        MMA(cacc[mf][nf], af[0][mf], bfr[1][nf]);   // hi*lo
                        MMA(cacc[mf][nf], af[1][mf], bfr[0][nf]);   // lo*hi
                    }
            }
        }

        // ---------- epilogue in registers: bias + relu + hi/lo split -> layer3 A frags ----------
        uint32_t Ah[2][2][4], Al[2][2][4];
        {
            const float* sb2 = (const float*)(smem + O_B2);
            #pragma unroll
            for (int nf = 0; nf < 4; nf++) {
                float bv0 = sb2[n0 + 8*nf + 2*t4];
                float bv1 = sb2[n0 + 8*nf + 2*t4 + 1];
                #pragma unroll
                for (int mf = 0; mf < 2; mf++) {
                    cacc[mf][nf][0] = fmaxf(cacc[mf][nf][0] + bv0, 0.0f);
                    cacc[mf][nf][1] = fmaxf(cacc[mf][nf][1] + bv1, 0.0f);
                    cacc[mf][nf][2] = fmaxf(cacc[mf][nf][2] + bv0, 0.0f);
                    cacc[mf][nf][3] = fmaxf(cacc[mf][nf][3] + bv1, 0.0f);
                }
            }
            #pragma unroll
            for (int mf = 0; mf < 2; mf++)
                #pragma unroll
                for (int kf = 0; kf < 2; kf++) {
                    const float* cL = cacc[mf][2*kf];
                    const float* cH = cacc[mf][2*kf+1];
                    #pragma unroll
                    for (int h = 0; h < 2; h++) {
                        float v0 = cL[2*h], v1 = cL[2*h+1];
                        float w0 = cH[2*h], w1 = cH[2*h+1];
                        __nv_bfloat16 b0 = __float2bfloat16_rn(v0);
                        __nv_bfloat16 b1_ = __float2bfloat16_rn(v1);
                        __nv_bfloat16 b2_ = __float2bfloat16_rn(w0);
                        __nv_bfloat16 b3_ = __float2bfloat16_rn(w1);
                        __nv_bfloat162 p0; p0.x = b0;  p0.y = b1_;
                        __nv_bfloat162 p1; p1.x = b2_; p1.y = b3_;
                        Ah[mf][kf][h]   = *(uint32_t*)&p0;
                        Ah[mf][kf][2+h] = *(uint32_t*)&p1;
                        Al[mf][kf][h]   = pack_bf16x2(v0 - __bfloat162float(b0),
                                                      v1 - __bfloat162float(b1_));
                        Al[mf][kf][2+h] = pack_bf16x2(w0 - __bfloat162float(b2_),
                                                      w1 - __bfloat162float(b3_));
                    }
                }
        }

        // ---------- layer 3: partial Z[32m x 32ch] over this warp's k-slice ----------
        float zacc[2][4][4];
        #pragma unroll
        for (int i = 0; i < 2; i++)
            #pragma unroll
            for (int j = 0; j < 4; j++)
                #pragma unroll
                for (int r = 0; r < 4; r++) zacc[i][j][r] = 0.0f;
        #pragma unroll
        for (int mf = 0; mf < 2; mf++)
            #pragma unroll
            for (int chf = 0; chf < 4; chf++)
                #pragma unroll
                for (int kf = 0; kf < 2; kf++) {
                    MMA(zacc[mf][chf], Ah[mf][kf], b3h[kf][chf]);
                    MMA(zacc[mf][chf], Ah[mf][kf], b3l[kf][chf]);
                    MMA(zacc[mf][chf], Al[mf][kf], b3h[kf][chf]);
                }

        __syncthreads();   // ldmatrix reads of A1/W2 done -> Zpart may alias A1

        // ---------- store partial Z: Zpart[wn][ch][132] ----------
        {
            float* zp = (float*)(smem + O_ZP) + wn * 4224;
            #pragma unroll
            for (int mf = 0; mf < 2; mf++)
                #pragma unroll
                for (int chf = 0; chf < 4; chf++) {
                    int ch = 8*chf + 2*t4;
                    int m  = m0 + 16*mf + g;
                    zp[ch*132 + m]         = zacc[mf][chf][0];
                    zp[(ch+1)*132 + m]     = zacc[mf][chf][1];
                    zp[ch*132 + m + 8]     = zacc[mf][chf][2];
                    zp[(ch+1)*132 + m + 8] = zacc[mf][chf][3];
                }
        }
        __syncthreads();

        // ---------- bitonic sorted-dot pool (2 channels per warp) ----------
        {
            const float* sb3 = (const float*)(smem + O_B3);
            const float* zp0 = (const float*)(smem + O_ZP);
            float* sPl = (float*)(smem + O_PL);
            #pragma unroll
            for (int cc = 0; cc < 2; cc++) {
                const int c = wid * 2 + cc;
                const float bias = sb3[c];
                float v[4];
                #pragma unroll
                for (int r = 0; r < 4; r++) {
                    int p = r*32 + lane;
                    v[r] = zp0[c*132 + p] + zp0[4224 + c*132 + p]
                         + zp0[8448 + c*132 + p] + zp0[12672 + c*132 + p] + bias;
                }
                #pragma unroll
                for (int k = 2; k <= 128; k <<= 1) {
                    #pragma unroll
                    for (int st = 64; st >= 1; st >>= 1) {
                        if (st >= k) continue;
                        if (st < 32) {
                            const bool lower = ((lane & st) == 0);
                            #pragma unroll
                            for (int r = 0; r < 4; r++) {
                                float o = __shfl_xor_sync(0xffffffffu, v[r], st);
                                bool up = (((r*32 + lane) & k) == 0);
                                bool tmin = (up == lower);
                                float mn = fminf(v[r], o), mx = fmaxf(v[r], o);
                                v[r] = tmin ? mn : mx;
                            }
                        } else if (st == 32) {
                            #pragma unroll
                            for (int ra = 0; ra < 4; ra += 2) {
                                bool up = (((ra*32) & k) == 0);
                                float mn = fminf(v[ra], v[ra+1]), mx = fmaxf(v[ra], v[ra+1]);
                                v[ra]   = up ? mn : mx;
                                v[ra+1] = up ? mx : mn;
                            }
                        } else {
                            #pragma unroll
                            for (int ra = 0; ra < 2; ra++) {
                                float mn = fminf(v[ra], v[ra+2]), mx = fmaxf(v[ra], v[ra+2]);
                                v[ra]   = mn;
                                v[ra+2] = mx;
                            }
                        }
                    }
                }
                const float* wc = sWp + c * 128;
                float sum = v[0] * wc[127 - lane]
                          + v[1] * wc[95  - lane]
                          + v[2] * wc[63  - lane]
                          + v[3] * wc[31  - lane];
                #pragma unroll
                for (int ofs = 16; ofs > 0; ofs >>= 1)
                    sum += __shfl_xor_sync(0xffffffffu, sum, ofs);
                if (lane == 0) sPl[c] = sum;
            }
        }
        __syncthreads();

        // ---------- reparameterize + write ----------
        if (tid < NLAT) {
            const float* sPl = (const float*)(smem + O_PL);
            float mu = sPl[2*tid];
            float lv = sPl[2*tid + 1];
            float e  = eps[(size_t)bset*NLAT + tid];
            float smp = fmaf(e, expf(0.5f * lv), mu);
            out[(size_t)bset*NLAT + tid] = mu;
            out[(size_t)(NBATCH*NLAT)   + (size_t)bset*NLAT + tid] = lv;
            out[(size_t)(2*NBATCH*NLAT) + (size_t)bset*NLAT + tid] = smp;
        }
        __syncthreads();   // sPl/Zpart reads done before next set overwrites
    }
}

extern "C" void kernel_launch(void* const* d_in, const int* in_sizes, int n_in,
                              void* d_out, int out_size) {
    const float* x   = (const float*)d_in[0];
    const float* W1  = (const float*)d_in[1];
    const float* b1  = (const float*)d_in[2];
    const float* W2  = (const float*)d_in[3];
    const float* b2  = (const float*)d_in[4];
    const float* W3  = (const float*)d_in[5];
    const float* b3  = (const float*)d_in[6];
    const float* pwm = (const float*)d_in[7];
    const float* eps = (const float*)d_in[8];
    float* out = (float*)d_out;

    cudaFuncSetAttribute(enc_kernel, cudaFuncAttributeMaxDynamicSharedMemorySize, SMEM_BYTES);
    enc_kernel<<<GRID, TPB, SMEM_BYTES>>>(x, W1, b1, W2, b2, W3, b3, pwm, eps, out);
}